// round 4
// baseline (speedup 1.0000x reference)
#include <cuda_runtime.h>
#include <cuda_bf16.h>
#include <cfloat>
#include <math.h>

// Problem constants
#define BS    16
#define CAP   64
#define VOCAB 50265
#define TOPK  5
#define SEQ   256
#define AT    32
#define D     768
#define END_ID 2

// Scratch (device globals — no allocation allowed)
__device__ float g_sce[BS * CAP * D];   // [16,64,768]
__device__ float g_att[BS * AT * D];    // [16,32,768]

// ---------------------------------------------------------------------------
// Kernel 1: per (b,c) row — top-5 over vocab, softmax, weighted embed gather.
// Grid: 1024 blocks (one per row), 256 threads.
// ---------------------------------------------------------------------------
__global__ __launch_bounds__(256) void topk_sce_kernel(
    const float* __restrict__ caption_out,   // [16,64,VOCAB]
    const float* __restrict__ embed_table)   // [VOCAB, D]
{
    const int row = blockIdx.x;              // 0..1023  (= b*CAP + c)
    const int t   = threadIdx.x;
    const float* rowp = caption_out + (size_t)row * VOCAB;

    // ---- per-thread top-5 in scalar registers (sorted desc) ----
    float v0 = -FLT_MAX, v1 = -FLT_MAX, v2 = -FLT_MAX, v3 = -FLT_MAX, v4 = -FLT_MAX;
    int   i0 = 0, i1 = 0, i2 = 0, i3 = 0, i4 = 0;

    #pragma unroll 4
    for (int e = t; e < VOCAB; e += 256) {
        float x = __ldg(rowp + e);
        if (x > v4) {
            v4 = x; i4 = e;
            if (v4 > v3) { float tv=v3; v3=v4; v4=tv; int ti=i3; i3=i4; i4=ti; }
            if (v3 > v2) { float tv=v2; v2=v3; v3=tv; int ti=i2; i2=i3; i3=ti; }
            if (v2 > v1) { float tv=v1; v1=v2; v2=tv; int ti=i1; i1=i2; i2=ti; }
            if (v1 > v0) { float tv=v0; v0=v1; v1=tv; int ti=i0; i0=i1; i1=ti; }
        }
    }

    // ---- dump 1280 candidates to shared ----
    __shared__ float cv[256 * TOPK];
    __shared__ int   ci[256 * TOPK];
    cv[t*5+0]=v0; cv[t*5+1]=v1; cv[t*5+2]=v2; cv[t*5+3]=v3; cv[t*5+4]=v4;
    ci[t*5+0]=i0; ci[t*5+1]=i1; ci[t*5+2]=i2; ci[t*5+3]=i3; ci[t*5+4]=i4;

    __shared__ float wmv[8];
    __shared__ int   wmp[8];
    __shared__ float fv[TOPK];
    __shared__ int   fi[TOPK];
    __syncthreads();

    const int lane = t & 31;
    const int wid  = t >> 5;

    // ---- 5 rounds of block-wide argmax over the candidate pool ----
    for (int r = 0; r < TOPK; r++) {
        // thread-local max over its 5 slots
        float bm = cv[t*5];
        int   bp = t*5;
        #pragma unroll
        for (int m = 1; m < 5; m++) {
            float c = cv[t*5+m];
            if (c > bm) { bm = c; bp = t*5+m; }
        }
        // warp reduce (val, pos)
        #pragma unroll
        for (int off = 16; off > 0; off >>= 1) {
            float ov = __shfl_down_sync(0xffffffffu, bm, off);
            int   op = __shfl_down_sync(0xffffffffu, bp, off);
            if (ov > bm) { bm = ov; bp = op; }
        }
        if (lane == 0) { wmv[wid] = bm; wmp[wid] = bp; }
        __syncthreads();
        if (t == 0) {
            float gm = wmv[0]; int gp = wmp[0];
            #pragma unroll
            for (int w = 1; w < 8; w++)
                if (wmv[w] > gm) { gm = wmv[w]; gp = wmp[w]; }
            fv[r] = gm;
            fi[r] = ci[gp];
            cv[gp] = -FLT_MAX;     // remove for next round
        }
        __syncthreads();
    }

    // ---- softmax over 5 (fv sorted desc so fv[0] is the max) ----
    float mx = fv[0];
    float p0 = __expf(fv[0]-mx), p1 = __expf(fv[1]-mx), p2 = __expf(fv[2]-mx),
          p3 = __expf(fv[3]-mx), p4 = __expf(fv[4]-mx);
    float inv = 1.0f / (p0+p1+p2+p3+p4);
    p0*=inv; p1*=inv; p2*=inv; p3*=inv; p4*=inv;

    const float* e0 = embed_table + (size_t)fi[0]*D;
    const float* e1 = embed_table + (size_t)fi[1]*D;
    const float* e2 = embed_table + (size_t)fi[2]*D;
    const float* e3 = embed_table + (size_t)fi[3]*D;
    const float* e4 = embed_table + (size_t)fi[4]*D;

    float* sce = g_sce + (size_t)row * D;
    #pragma unroll
    for (int j = 0; j < 3; j++) {
        int d = t + j*256;
        sce[d] = p0*e0[d] + p1*e1[d] + p2*e2[d] + p3*e3[d] + p4*e4[d];
    }
}

// ---------------------------------------------------------------------------
// Kernel 2: attention. Block = (b, query-group of 8). Grid 64, 256 threads.
// ---------------------------------------------------------------------------
__global__ __launch_bounds__(256) void attn_kernel(
    const float* __restrict__ q_in,          // [16,32,768]
    const int*   __restrict__ caption_len)   // [16]
{
    const int b  = blockIdx.x >> 2;
    const int qg = blockIdx.x & 3;           // queries qg*8 .. qg*8+7
    const int t  = threadIdx.x;

    const float* sce = g_sce + (size_t)b * CAP * D;

    __shared__ float sq[8 * D];              // 24 KB
    __shared__ float ssc[8][CAP];            // scores -> attn weights

    // stage the 8 query rows
    const float4* qg4 = (const float4*)(q_in + ((size_t)b * AT + qg*8) * D);
    float4* sq4 = (float4*)sq;
    for (int i = t; i < 8*D/4; i += 256) sq4[i] = qg4[i];
    __syncthreads();

    // scores: 512 (q,k) pairs, each thread fully owns 2 dot products
    for (int p = t; p < 512; p += 256) {
        const int qi = p >> 6;
        const int k  = p & 63;
        const float4* srow = (const float4*)(sce + (size_t)k * D);
        const float4* qrow = (const float4*)(sq + qi * D);
        float acc = 0.0f;
        #pragma unroll 4
        for (int j = 0; j < D/4; j++) {
            float4 a = srow[j];
            float4 qq = qrow[j];
            acc += a.x*qq.x + a.y*qq.y + a.z*qq.z + a.w*qq.w;
        }
        ssc[qi][k] = acc;
    }
    __syncthreads();

    // softmax per query row; warp w handles row w
    const int w = t >> 5, lane = t & 31;
    const int clen = caption_len[b];
    const float scale = 1.0f / sqrtf((float)D);
    float s0 = (lane      < clen) ? ssc[w][lane]      * scale : -1e9f;
    float s1 = (lane + 32 < clen) ? ssc[w][lane + 32] * scale : -1e9f;
    float mx = fmaxf(s0, s1);
    #pragma unroll
    for (int off = 16; off > 0; off >>= 1)
        mx = fmaxf(mx, __shfl_xor_sync(0xffffffffu, mx, off));
    float e0 = __expf(s0 - mx), e1 = __expf(s1 - mx);
    float sum = e0 + e1;
    #pragma unroll
    for (int off = 16; off > 0; off >>= 1)
        sum += __shfl_xor_sync(0xffffffffu, sum, off);
    float isum = 1.0f / sum;
    ssc[w][lane]      = e0 * isum;
    ssc[w][lane + 32] = e1 * isum;
    __syncthreads();

    // output: thread owns dims t, t+256, t+512 for all 8 queries
    float acc[8][3];
    #pragma unroll
    for (int qi = 0; qi < 8; qi++) { acc[qi][0]=0; acc[qi][1]=0; acc[qi][2]=0; }

    for (int k = 0; k < CAP; k++) {
        const float* srow = sce + (size_t)k * D;
        float a0 = srow[t], a1 = srow[t + 256], a2 = srow[t + 512];
        #pragma unroll
        for (int qi = 0; qi < 8; qi++) {
            float aw = ssc[qi][k];
            acc[qi][0] = fmaf(aw, a0, acc[qi][0]);
            acc[qi][1] = fmaf(aw, a1, acc[qi][1]);
            acc[qi][2] = fmaf(aw, a2, acc[qi][2]);
        }
    }
    #pragma unroll
    for (int qi = 0; qi < 8; qi++) {
        float* orow = g_att + ((size_t)b * AT + qg*8 + qi) * D;
        orow[t]       = acc[qi][0];
        orow[t + 256] = acc[qi][1];
        orow[t + 512] = acc[qi][2];
    }
}

// ---------------------------------------------------------------------------
// Kernel 3: final assembly. Block per (b,s). Grid 4096, 192 threads (float4).
// ---------------------------------------------------------------------------
__global__ __launch_bounds__(192) void assemble_kernel(
    const float* __restrict__ embed_table,
    const int*   __restrict__ input_ids,     // [16,256]
    const int*   __restrict__ origin_len,    // [16]
    const int*   __restrict__ target_len,    // [16]
    float*       __restrict__ out)           // [16,256,768]
{
    const int bs = blockIdx.x;
    const int b  = bs >> 8;
    const int s  = bs & 255;
    const int rel = s - origin_len[b];
    const int tl  = target_len[b];

    const float* src;
    if (rel >= 0 && rel < tl)      src = g_att + ((size_t)b * AT + rel) * D;
    else if (rel == tl)            src = embed_table + (size_t)END_ID * D;
    else                           src = embed_table + (size_t)input_ids[bs] * D;

    ((float4*)(out + (size_t)bs * D))[threadIdx.x] = ((const float4*)src)[threadIdx.x];
}

// ---------------------------------------------------------------------------
extern "C" void kernel_launch(void* const* d_in, const int* in_sizes, int n_in,
                              void* d_out, int out_size)
{
    const float* caption_out      = (const float*)d_in[0];   // [16,64,50265]
    const float* embed_table      = (const float*)d_in[1];   // [50265,768]
    const float* inputs_embeds_at = (const float*)d_in[2];   // [16,32,768]
    const int*   input_ids        = (const int*)  d_in[3];   // [16,256]
    const int*   origin_len       = (const int*)  d_in[4];   // [16]
    const int*   target_len       = (const int*)  d_in[5];   // [16]
    const int*   caption_len      = (const int*)  d_in[6];   // [16]
    float* out = (float*)d_out;

    topk_sce_kernel<<<BS * CAP, 256>>>(caption_out, embed_table);
    attn_kernel<<<BS * 4, 256>>>(inputs_embeds_at, caption_len);
    assemble_kernel<<<BS * SEQ, 192>>>(embed_table, input_ids,
                                       origin_len, target_len, out);
}

// round 5
// speedup vs baseline: 1.7699x; 1.7699x over previous
#include <cuda_runtime.h>
#include <cuda_bf16.h>
#include <cfloat>
#include <math.h>

// Problem constants
#define BS    16
#define CAP   64
#define VOCAB 50265
#define TOPK  5
#define SEQ   256
#define AT    32
#define D     768
#define END_ID 2

#define QPAD  772   // padded q-row stride in floats (772%32=4 -> conflict-free)

// Scratch (device globals — no allocation allowed)
__device__ float g_sce[BS * CAP * D];   // [16,64,768]
__device__ float g_att[BS * AT * D];    // [16,32,768]

// ---------------------------------------------------------------------------
// Kernel 1: per (b,c) row — top-5 over vocab, softmax, weighted embed gather.
// Grid: 1024 blocks (one per row), 256 threads. float4 scan + max4 prefilter.
// ---------------------------------------------------------------------------
struct Top5 {
    float v0, v1, v2, v3, v4;
    int   i0, i1, i2, i3, i4;
    __device__ __forceinline__ void ins(float x, int e) {
        if (x > v4) {
            v4 = x; i4 = e;
            if (v4 > v3) { float tv=v3; v3=v4; v4=tv; int ti=i3; i3=i4; i4=ti; }
            if (v3 > v2) { float tv=v2; v2=v3; v3=tv; int ti=i2; i2=i3; i3=ti; }
            if (v2 > v1) { float tv=v1; v1=v2; v2=tv; int ti=i1; i1=i2; i2=ti; }
            if (v1 > v0) { float tv=v0; v0=v1; v1=tv; int ti=i0; i0=i1; i1=ti; }
        }
    }
};

__global__ __launch_bounds__(256) void topk_sce_kernel(
    const float* __restrict__ caption_out,   // [16,64,VOCAB]
    const float* __restrict__ embed_table)   // [VOCAB, D]
{
    const int row = blockIdx.x;              // 0..1023  (= b*CAP + c)
    const int t   = threadIdx.x;
    const float* rowp = caption_out + (size_t)row * VOCAB;

    Top5 tk;
    tk.v0 = tk.v1 = tk.v2 = tk.v3 = tk.v4 = -FLT_MAX;
    tk.i0 = tk.i1 = tk.i2 = tk.i3 = tk.i4 = 0;

    // alignment prologue: rows are (row % 4) floats off 16B alignment
    const int mis = (int)(((size_t)rowp >> 2) & 3);   // misalignment in floats
    const int pre = (4 - mis) & 3;                    // scalar prefix count (0..3)
    const int n4  = (VOCAB - pre) >> 2;               // aligned float4 count
    const int tail_start = pre + 4 * n4;              // scalar tail start

    if (t < pre) tk.ins(rowp[t], t);
    if (t >= 32 && t < 32 + (VOCAB - tail_start)) {
        int e = tail_start + (t - 32);
        tk.ins(rowp[e], e);
    }

    const float4* base4 = (const float4*)(rowp + pre);
    #pragma unroll 2
    for (int e = t; e < n4; e += 256) {
        float4 x = base4[e];
        float m = fmaxf(fmaxf(x.x, x.y), fmaxf(x.z, x.w));
        if (m > tk.v4) {                      // rare path
            int b = pre + 4 * e;
            tk.ins(x.x, b); tk.ins(x.y, b+1); tk.ins(x.z, b+2); tk.ins(x.w, b+3);
        }
    }

    // ---- dump 1280 candidates to shared ----
    __shared__ float cv[256 * TOPK];
    __shared__ int   ci[256 * TOPK];
    cv[t*5+0]=tk.v0; cv[t*5+1]=tk.v1; cv[t*5+2]=tk.v2; cv[t*5+3]=tk.v3; cv[t*5+4]=tk.v4;
    ci[t*5+0]=tk.i0; ci[t*5+1]=tk.i1; ci[t*5+2]=tk.i2; ci[t*5+3]=tk.i3; ci[t*5+4]=tk.i4;

    __shared__ float wmv[8];
    __shared__ int   wmp[8];
    __shared__ float fv[TOPK];
    __shared__ int   fi[TOPK];
    __syncthreads();

    const int lane = t & 31;
    const int wid  = t >> 5;

    // ---- 5 rounds of block-wide argmax over the candidate pool ----
    for (int r = 0; r < TOPK; r++) {
        float bm = cv[t*5];
        int   bp = t*5;
        #pragma unroll
        for (int m = 1; m < 5; m++) {
            float c = cv[t*5+m];
            if (c > bm) { bm = c; bp = t*5+m; }
        }
        #pragma unroll
        for (int off = 16; off > 0; off >>= 1) {
            float ov = __shfl_down_sync(0xffffffffu, bm, off);
            int   op = __shfl_down_sync(0xffffffffu, bp, off);
            if (ov > bm) { bm = ov; bp = op; }
        }
        if (lane == 0) { wmv[wid] = bm; wmp[wid] = bp; }
        __syncthreads();
        if (t == 0) {
            float gm = wmv[0]; int gp = wmp[0];
            #pragma unroll
            for (int w = 1; w < 8; w++)
                if (wmv[w] > gm) { gm = wmv[w]; gp = wmp[w]; }
            fv[r] = gm;
            fi[r] = ci[gp];
            cv[gp] = -FLT_MAX;
        }
        __syncthreads();
    }

    // ---- softmax over 5 (fv sorted desc so fv[0] is the max) ----
    float mx = fv[0];
    float p0 = __expf(fv[0]-mx), p1 = __expf(fv[1]-mx), p2 = __expf(fv[2]-mx),
          p3 = __expf(fv[3]-mx), p4 = __expf(fv[4]-mx);
    float inv = 1.0f / (p0+p1+p2+p3+p4);
    p0*=inv; p1*=inv; p2*=inv; p3*=inv; p4*=inv;

    const float* e0 = embed_table + (size_t)fi[0]*D;
    const float* e1 = embed_table + (size_t)fi[1]*D;
    const float* e2 = embed_table + (size_t)fi[2]*D;
    const float* e3 = embed_table + (size_t)fi[3]*D;
    const float* e4 = embed_table + (size_t)fi[4]*D;

    float* sce = g_sce + (size_t)row * D;
    #pragma unroll
    for (int j = 0; j < 3; j++) {
        int d = t + j*256;
        sce[d] = p0*e0[d] + p1*e1[d] + p2*e2[d] + p3*e3[d] + p4*e4[d];
    }
}

// ---------------------------------------------------------------------------
// Kernel 2: attention. Block = (b, query-group of 8). Grid 64, 256 threads.
// Score loads coalesced: 8 lanes share a k-row (broadcast), qi from padded smem.
// ---------------------------------------------------------------------------
__global__ __launch_bounds__(256) void attn_kernel(
    const float* __restrict__ q_in,          // [16,32,768]
    const int*   __restrict__ caption_len)   // [16]
{
    const int b  = blockIdx.x >> 2;
    const int qg = blockIdx.x & 3;           // queries qg*8 .. qg*8+7
    const int t  = threadIdx.x;

    const float* sce = g_sce + (size_t)b * CAP * D;

    __shared__ float sq[8 * QPAD];           // padded query rows (~24.7 KB)
    __shared__ float ssc[8][CAP];            // scores -> attn weights

    // stage the 8 query rows with padded stride
    {
        const float4* qg4 = (const float4*)(q_in + ((size_t)b * AT + qg*8) * D);
        for (int i = t; i < 8 * (D/4); i += 256) {
            int qi = i / (D/4), j = i % (D/4);
            *(float4*)&sq[qi * QPAD + j * 4] = qg4[qi * (D/4) + j];
        }
    }
    __syncthreads();

    // scores: 512 (q,k) pairs; p -> (k = p>>3, qi = p&7) so 8 lanes share k.
    #pragma unroll
    for (int pp = 0; pp < 2; pp++) {
        const int p  = t + pp * 256;
        const int k  = p >> 3;
        const int qi = p & 7;
        const float4* krow = (const float4*)(sce + (size_t)k * D);
        const float4* qrow = (const float4*)(sq + qi * QPAD);
        float a0 = 0.f, a1 = 0.f, a2 = 0.f, a3 = 0.f;
        #pragma unroll 4
        for (int j = 0; j < D/4; j++) {
            float4 kk = krow[j];
            float4 qq = qrow[j];
            a0 = fmaf(kk.x, qq.x, a0);
            a1 = fmaf(kk.y, qq.y, a1);
            a2 = fmaf(kk.z, qq.z, a2);
            a3 = fmaf(kk.w, qq.w, a3);
        }
        ssc[qi][k] = (a0 + a1) + (a2 + a3);
    }
    __syncthreads();

    // softmax per query row; warp w handles row w
    const int w = t >> 5, lane = t & 31;
    const int clen = caption_len[b];
    const float scale = 1.0f / sqrtf((float)D);
    float s0 = (lane      < clen) ? ssc[w][lane]      * scale : -1e9f;
    float s1 = (lane + 32 < clen) ? ssc[w][lane + 32] * scale : -1e9f;
    float mx = fmaxf(s0, s1);
    #pragma unroll
    for (int off = 16; off > 0; off >>= 1)
        mx = fmaxf(mx, __shfl_xor_sync(0xffffffffu, mx, off));
    float e0 = __expf(s0 - mx), e1 = __expf(s1 - mx);
    float sum = e0 + e1;
    #pragma unroll
    for (int off = 16; off > 0; off >>= 1)
        sum += __shfl_xor_sync(0xffffffffu, sum, off);
    float isum = 1.0f / sum;
    ssc[w][lane]      = e0 * isum;
    ssc[w][lane + 32] = e1 * isum;
    __syncthreads();

    // output: thread owns dims t, t+256, t+512 for all 8 queries (coalesced)
    float acc[8][3];
    #pragma unroll
    for (int qi = 0; qi < 8; qi++) { acc[qi][0]=0; acc[qi][1]=0; acc[qi][2]=0; }

    #pragma unroll 2
    for (int k = 0; k < CAP; k++) {
        const float* srow = sce + (size_t)k * D;
        float a0 = srow[t], a1 = srow[t + 256], a2 = srow[t + 512];
        #pragma unroll
        for (int qi = 0; qi < 8; qi++) {
            float aw = ssc[qi][k];
            acc[qi][0] = fmaf(aw, a0, acc[qi][0]);
            acc[qi][1] = fmaf(aw, a1, acc[qi][1]);
            acc[qi][2] = fmaf(aw, a2, acc[qi][2]);
        }
    }
    #pragma unroll
    for (int qi = 0; qi < 8; qi++) {
        float* orow = g_att + ((size_t)b * AT + qg*8 + qi) * D;
        orow[t]       = acc[qi][0];
        orow[t + 256] = acc[qi][1];
        orow[t + 512] = acc[qi][2];
    }
}

// ---------------------------------------------------------------------------
// Kernel 3: final assembly. Block per (b,s). Grid 4096, 192 threads (float4).
// ---------------------------------------------------------------------------
__global__ __launch_bounds__(192) void assemble_kernel(
    const float* __restrict__ embed_table,
    const int*   __restrict__ input_ids,     // [16,256]
    const int*   __restrict__ origin_len,    // [16]
    const int*   __restrict__ target_len,    // [16]
    float*       __restrict__ out)           // [16,256,768]
{
    const int bs = blockIdx.x;
    const int b  = bs >> 8;
    const int s  = bs & 255;
    const int rel = s - origin_len[b];
    const int tl  = target_len[b];

    const float* src;
    if (rel >= 0 && rel < tl)      src = g_att + ((size_t)b * AT + rel) * D;
    else if (rel == tl)            src = embed_table + (size_t)END_ID * D;
    else                           src = embed_table + (size_t)input_ids[bs] * D;

    ((float4*)(out + (size_t)bs * D))[threadIdx.x] = ((const float4*)src)[threadIdx.x];
}

// ---------------------------------------------------------------------------
extern "C" void kernel_launch(void* const* d_in, const int* in_sizes, int n_in,
                              void* d_out, int out_size)
{
    const float* caption_out      = (const float*)d_in[0];   // [16,64,50265]
    const float* embed_table      = (const float*)d_in[1];   // [50265,768]
    const float* inputs_embeds_at = (const float*)d_in[2];   // [16,32,768]
    const int*   input_ids        = (const int*)  d_in[3];   // [16,256]
    const int*   origin_len       = (const int*)  d_in[4];   // [16]
    const int*   target_len       = (const int*)  d_in[5];   // [16]
    const int*   caption_len      = (const int*)  d_in[6];   // [16]
    float* out = (float*)d_out;

    topk_sce_kernel<<<BS * CAP, 256>>>(caption_out, embed_table);
    attn_kernel<<<BS * 4, 256>>>(inputs_embeds_at, caption_len);
    assemble_kernel<<<BS * SEQ, 192>>>(embed_table, input_ids,
                                       origin_len, target_len, out);
}

// round 6
// speedup vs baseline: 1.9069x; 1.0774x over previous
#include <cuda_runtime.h>
#include <cuda_bf16.h>
#include <cfloat>
#include <math.h>

// Problem constants
#define BS    16
#define CAP   64
#define VOCAB 50265
#define TOPK  5
#define SEQ   256
#define AT    32
#define D     768
#define END_ID 2

#define QPAD  772   // padded q-row stride in floats (772%32=4 -> conflict-free)

// Scratch (device globals — no allocation allowed)
__device__ float g_sce[BS * CAP * D];   // [16,64,768]
__device__ float g_att[BS * AT * D];    // [16,32,768]

// ---------------------------------------------------------------------------
// Kernel 1: per (b,c) row — top-5 over vocab, softmax, weighted embed gather.
// Grid: 1024 blocks (one per row), 256 threads.
// Hot loop: 16-element chunks, block-shared threshold kills the slow path.
// ---------------------------------------------------------------------------
struct Top5 {
    float v0, v1, v2, v3, v4;
    int   i0, i1, i2, i3, i4;
    __device__ __forceinline__ void ins(float x, int e) {
        if (x > v4) {
            v4 = x; i4 = e;
            if (v4 > v3) { float tv=v3; v3=v4; v4=tv; int ti=i3; i3=i4; i4=ti; }
            if (v3 > v2) { float tv=v2; v2=v3; v3=tv; int ti=i2; i2=i3; i3=ti; }
            if (v2 > v1) { float tv=v1; v1=v2; v2=tv; int ti=i1; i1=i2; i2=ti; }
            if (v1 > v0) { float tv=v0; v0=v1; v1=tv; int ti=i0; i0=i1; i1=ti; }
        }
    }
    __device__ __forceinline__ void ins4(const float4& x, int b) {
        ins(x.x, b); ins(x.y, b+1); ins(x.z, b+2); ins(x.w, b+3);
    }
};

__device__ __forceinline__ float max4(const float4& x) {
    return fmaxf(fmaxf(x.x, x.y), fmaxf(x.z, x.w));
}

__global__ __launch_bounds__(256) void topk_sce_kernel(
    const float* __restrict__ caption_out,   // [16,64,VOCAB]
    const float* __restrict__ embed_table)   // [VOCAB, D]
{
    const int row = blockIdx.x;              // 0..1023  (= b*CAP + c)
    const int t   = threadIdx.x;
    const float* rowp = caption_out + (size_t)row * VOCAB;

    // Shared monotone-ish filter threshold. Benign races only ever LOWER it
    // temporarily (extra work, never wrong): any stored value is some thread's
    // local 5th-best, so >=5 elements >= T exist in the candidate pool, and
    // anything <= T provably cannot be in the block top-5.
    volatile __shared__ float sT;
    if (t == 0) sT = -FLT_MAX;

    Top5 tk;
    tk.v0 = tk.v1 = tk.v2 = tk.v3 = tk.v4 = -FLT_MAX;
    tk.i0 = tk.i1 = tk.i2 = tk.i3 = tk.i4 = 0;

    // alignment prologue: rows are (row % 4) floats off 16B alignment
    const int mis = (int)(((size_t)rowp >> 2) & 3);
    const int pre = (4 - mis) & 3;                    // scalar prefix (0..3)
    const int n4  = (VOCAB - pre) >> 2;               // aligned float4 count
    const int tail_start = pre + 4 * n4;              // scalar tail start
    __syncthreads();                                  // sT visible

    if (t < pre) tk.ins(rowp[t], t);
    if (t >= 32 && t < 32 + (VOCAB - tail_start)) {
        int e = tail_start + (t - 32);
        tk.ins(rowp[e], e);
    }

    const float4* base4 = (const float4*)(rowp + pre);
    const int nchunks = n4 >> 10;                     // chunks of 1024 float4s

    for (int i = 0; i < nchunks; i++) {
        const int e = t + (i << 10);
        float4 x0 = base4[e];
        float4 x1 = base4[e + 256];
        float4 x2 = base4[e + 512];
        float4 x3 = base4[e + 768];
        float m = fmaxf(fmaxf(max4(x0), max4(x1)), fmaxf(max4(x2), max4(x3)));
        float thr = fmaxf(tk.v4, sT);
        if (m > thr) {                                // rare after warmup
            tk.ins4(x0, pre + 4*e);
            tk.ins4(x1, pre + 4*(e + 256));
            tk.ins4(x2, pre + 4*(e + 512));
            tk.ins4(x3, pre + 4*(e + 768));
            if (tk.v4 > sT) sT = tk.v4;
        }
    }
    // remainder float4s
    for (int e = (nchunks << 10) + t; e < n4; e += 256) {
        float4 x = base4[e];
        float m = max4(x);
        if (m > fmaxf(tk.v4, sT)) tk.ins4(x, pre + 4*e);
    }

    // ---- dump 1280 candidates to shared ----
    __shared__ float cv[256 * TOPK];
    __shared__ int   ci[256 * TOPK];
    cv[t*5+0]=tk.v0; cv[t*5+1]=tk.v1; cv[t*5+2]=tk.v2; cv[t*5+3]=tk.v3; cv[t*5+4]=tk.v4;
    ci[t*5+0]=tk.i0; ci[t*5+1]=tk.i1; ci[t*5+2]=tk.i2; ci[t*5+3]=tk.i3; ci[t*5+4]=tk.i4;

    __shared__ float wmv[8];
    __shared__ int   wmp[8];
    __shared__ float fv[TOPK];
    __shared__ int   fi[TOPK];
    __syncthreads();

    const int lane = t & 31;
    const int wid  = t >> 5;

    // ---- 5 rounds of block-wide argmax over the candidate pool ----
    for (int r = 0; r < TOPK; r++) {
        float bm = cv[t*5];
        int   bp = t*5;
        #pragma unroll
        for (int m = 1; m < 5; m++) {
            float c = cv[t*5+m];
            if (c > bm) { bm = c; bp = t*5+m; }
        }
        #pragma unroll
        for (int off = 16; off > 0; off >>= 1) {
            float ov = __shfl_down_sync(0xffffffffu, bm, off);
            int   op = __shfl_down_sync(0xffffffffu, bp, off);
            if (ov > bm) { bm = ov; bp = op; }
        }
        if (lane == 0) { wmv[wid] = bm; wmp[wid] = bp; }
        __syncthreads();
        if (t == 0) {
            float gm = wmv[0]; int gp = wmp[0];
            #pragma unroll
            for (int w = 1; w < 8; w++)
                if (wmv[w] > gm) { gm = wmv[w]; gp = wmp[w]; }
            fv[r] = gm;
            fi[r] = ci[gp];
            cv[gp] = -FLT_MAX;
        }
        __syncthreads();
    }

    // ---- softmax over 5 (fv sorted desc so fv[0] is the max) ----
    float mx = fv[0];
    float p0 = __expf(fv[0]-mx), p1 = __expf(fv[1]-mx), p2 = __expf(fv[2]-mx),
          p3 = __expf(fv[3]-mx), p4 = __expf(fv[4]-mx);
    float inv = 1.0f / (p0+p1+p2+p3+p4);
    p0*=inv; p1*=inv; p2*=inv; p3*=inv; p4*=inv;

    const float* e0 = embed_table + (size_t)fi[0]*D;
    const float* e1 = embed_table + (size_t)fi[1]*D;
    const float* e2 = embed_table + (size_t)fi[2]*D;
    const float* e3 = embed_table + (size_t)fi[3]*D;
    const float* e4 = embed_table + (size_t)fi[4]*D;

    float* sce = g_sce + (size_t)row * D;
    #pragma unroll
    for (int j = 0; j < 3; j++) {
        int d = t + j*256;
        sce[d] = p0*e0[d] + p1*e1[d] + p2*e2[d] + p3*e3[d] + p4*e4[d];
    }
}

// ---------------------------------------------------------------------------
// Kernel 2: attention. Block = (b, query-group of 4). Grid 128, 256 threads.
// ---------------------------------------------------------------------------
__global__ __launch_bounds__(256) void attn_kernel(
    const float* __restrict__ q_in,          // [16,32,768]
    const int*   __restrict__ caption_len)   // [16]
{
    const int b  = blockIdx.x >> 3;
    const int qg = blockIdx.x & 7;           // queries qg*4 .. qg*4+3
    const int t  = threadIdx.x;

    const float* sce = g_sce + (size_t)b * CAP * D;

    __shared__ float sq[4 * QPAD];           // padded query rows (~12.4 KB)
    __shared__ float ssc[4][CAP];            // scores -> attn weights

    // stage the 4 query rows with padded stride
    {
        const float4* qg4 = (const float4*)(q_in + ((size_t)b * AT + qg*4) * D);
        for (int i = t; i < 4 * (D/4); i += 256) {
            int qi = i / (D/4), j = i % (D/4);
            *(float4*)&sq[qi * QPAD + j * 4] = qg4[qi * (D/4) + j];
        }
    }
    __syncthreads();

    // scores: 256 (q,k) pairs = 1 per thread; k = t>>2 so 4 lanes share a k-row
    {
        const int k  = t >> 2;
        const int qi = t & 3;
        const float4* krow = (const float4*)(sce + (size_t)k * D);
        const float4* qrow = (const float4*)(sq + qi * QPAD);
        float a0 = 0.f, a1 = 0.f, a2 = 0.f, a3 = 0.f;
        #pragma unroll 4
        for (int j = 0; j < D/4; j++) {
            float4 kk = krow[j];
            float4 qq = qrow[j];
            a0 = fmaf(kk.x, qq.x, a0);
            a1 = fmaf(kk.y, qq.y, a1);
            a2 = fmaf(kk.z, qq.z, a2);
            a3 = fmaf(kk.w, qq.w, a3);
        }
        ssc[qi][k] = (a0 + a1) + (a2 + a3);
    }
    __syncthreads();

    // softmax per query row; warps 0-3 handle rows 0-3
    const int w = t >> 5, lane = t & 31;
    const int clen = caption_len[b];
    if (w < 4) {
        const float scale = 1.0f / sqrtf((float)D);
        float s0 = (lane      < clen) ? ssc[w][lane]      * scale : -1e9f;
        float s1 = (lane + 32 < clen) ? ssc[w][lane + 32] * scale : -1e9f;
        float mx = fmaxf(s0, s1);
        #pragma unroll
        for (int off = 16; off > 0; off >>= 1)
            mx = fmaxf(mx, __shfl_xor_sync(0xffffffffu, mx, off));
        float e0 = __expf(s0 - mx), e1 = __expf(s1 - mx);
        float sum = e0 + e1;
        #pragma unroll
        for (int off = 16; off > 0; off >>= 1)
            sum += __shfl_xor_sync(0xffffffffu, sum, off);
        float isum = 1.0f / sum;
        ssc[w][lane]      = e0 * isum;
        ssc[w][lane + 32] = e1 * isum;
    }
    __syncthreads();

    // output: thread owns dims t, t+256, t+512 for all 4 queries (coalesced)
    float acc[4][3];
    #pragma unroll
    for (int qi = 0; qi < 4; qi++) { acc[qi][0]=0; acc[qi][1]=0; acc[qi][2]=0; }

    #pragma unroll 2
    for (int k = 0; k < CAP; k++) {
        const float* srow = sce + (size_t)k * D;
        float a0 = srow[t], a1 = srow[t + 256], a2 = srow[t + 512];
        #pragma unroll
        for (int qi = 0; qi < 4; qi++) {
            float aw = ssc[qi][k];
            acc[qi][0] = fmaf(aw, a0, acc[qi][0]);
            acc[qi][1] = fmaf(aw, a1, acc[qi][1]);
            acc[qi][2] = fmaf(aw, a2, acc[qi][2]);
        }
    }
    #pragma unroll
    for (int qi = 0; qi < 4; qi++) {
        float* orow = g_att + ((size_t)b * AT + qg*4 + qi) * D;
        orow[t]       = acc[qi][0];
        orow[t + 256] = acc[qi][1];
        orow[t + 512] = acc[qi][2];
    }
}

// ---------------------------------------------------------------------------
// Kernel 3: final assembly. Block per (b,s). Grid 4096, 192 threads (float4).
// ---------------------------------------------------------------------------
__global__ __launch_bounds__(192) void assemble_kernel(
    const float* __restrict__ embed_table,
    const int*   __restrict__ input_ids,     // [16,256]
    const int*   __restrict__ origin_len,    // [16]
    const int*   __restrict__ target_len,    // [16]
    float*       __restrict__ out)           // [16,256,768]
{
    const int bs = blockIdx.x;
    const int b  = bs >> 8;
    const int s  = bs & 255;
    const int rel = s - origin_len[b];
    const int tl  = target_len[b];

    const float* src;
    if (rel >= 0 && rel < tl)      src = g_att + ((size_t)b * AT + rel) * D;
    else if (rel == tl)            src = embed_table + (size_t)END_ID * D;
    else                           src = embed_table + (size_t)input_ids[bs] * D;

    ((float4*)(out + (size_t)bs * D))[threadIdx.x] = ((const float4*)src)[threadIdx.x];
}

// ---------------------------------------------------------------------------
extern "C" void kernel_launch(void* const* d_in, const int* in_sizes, int n_in,
                              void* d_out, int out_size)
{
    const float* caption_out      = (const float*)d_in[0];   // [16,64,50265]
    const float* embed_table      = (const float*)d_in[1];   // [50265,768]
    const float* inputs_embeds_at = (const float*)d_in[2];   // [16,32,768]
    const int*   input_ids        = (const int*)  d_in[3];   // [16,256]
    const int*   origin_len       = (const int*)  d_in[4];   // [16]
    const int*   target_len       = (const int*)  d_in[5];   // [16]
    const int*   caption_len      = (const int*)  d_in[6];   // [16]
    float* out = (float*)d_out;

    topk_sce_kernel<<<BS * CAP, 256>>>(caption_out, embed_table);
    attn_kernel<<<BS * 8, 256>>>(inputs_embeds_at, caption_len);
    assemble_kernel<<<BS * SEQ, 192>>>(embed_table, input_ids,
                                       origin_len, target_len, out);
}

// round 8
// speedup vs baseline: 2.2828x; 1.1972x over previous
#include <cuda_runtime.h>
#include <cuda_bf16.h>
#include <cfloat>
#include <math.h>

// Problem constants
#define BS    16
#define CAP   64
#define VOCAB 50265
#define TOPK  5
#define SEQ   256
#define AT    32
#define D     768
#define END_ID 2

#define QPAD  772      // padded q-row stride in floats
#define NCHUNK 12      // 12 * 1024 float4s = 12288 float4s in chunked region
#define CANDCAP 512    // candidate buffer capacity

// Scratch (device globals — no allocation allowed)
__device__ float g_sce[BS * CAP * D];   // [16,64,768]
__device__ float g_att[BS * AT * D];    // [16,32,768]

__device__ __forceinline__ float max4(const float4& x) {
    return fmaxf(fmaxf(x.x, x.y), fmaxf(x.z, x.w));
}

// ---------------------------------------------------------------------------
// Kernel 1: per (b,c) row — top-5 over vocab, softmax, weighted embed gather.
// Grid: 1024 blocks (one per row), 256 threads.
// Pass A: branchless max scan + per-chunk maxes to smem.
// Threshold T = 5th largest of the 8 warp maxes (provably safe: those are 5
// distinct elements >= T). Pass B: re-read only qualifying chunks (~17),
// push candidates to a small buffer, then 5 rounds of block argmax.
// ---------------------------------------------------------------------------
__global__ __launch_bounds__(256) void topk_sce_kernel(
    const float* __restrict__ caption_out,   // [16,64,VOCAB]
    const float* __restrict__ embed_table)   // [VOCAB, D]
{
    const int row = blockIdx.x;              // 0..1023  (= b*CAP + c)
    const int t   = threadIdx.x;
    const float* rowp = caption_out + (size_t)row * VOCAB;

    __shared__ float schunk[NCHUNK * 256];   // per-chunk maxes (12 KB)
    __shared__ float bv[CANDCAP];
    __shared__ int   bi[CANDCAP];
    __shared__ int   scnt;
    __shared__ float wmax[8];
    __shared__ float sTh;
    __shared__ float fv[TOPK];
    __shared__ int   fi[TOPK];

    if (t == 0) scnt = 0;

    // alignment prologue: rows are (row % 4)*VOCAB... floats off 16B alignment
    const int mis = (int)(((size_t)rowp >> 2) & 3);
    const int pre = (4 - mis) & 3;                    // scalar prefix (0..3)
    const int n4  = (VOCAB - pre) >> 2;               // aligned float4 count (>=12288)
    const int tail_start = pre + (n4 << 2);
    const int ntail = VOCAB - tail_start;             // 0..3
    const float4* base4 = (const float4*)(rowp + pre);

    // ================= Pass A: branchless max scan =================
    float m0 = -FLT_MAX, m1 = -FLT_MAX;
    #pragma unroll 2
    for (int i = 0; i < NCHUNK; i++) {
        const int e = t + (i << 10);
        float4 x0 = base4[e];
        float4 x1 = base4[e + 256];
        float4 x2 = base4[e + 512];
        float4 x3 = base4[e + 768];
        float cm = fmaxf(fmaxf(max4(x0), max4(x1)), fmaxf(max4(x2), max4(x3)));
        schunk[(i << 8) + t] = cm;
        m0 = fmaxf(m0, cm);
    }
    // remainder float4s
    for (int e = (NCHUNK << 10) + t; e < n4; e += 256)
        m1 = fmaxf(m1, max4(base4[e]));
    // scalar prefix / tail
    if (t < pre) m1 = fmaxf(m1, rowp[t]);
    if (t >= 32 && t < 32 + ntail) m1 = fmaxf(m1, rowp[tail_start + (t - 32)]);

    float runMax = fmaxf(m0, m1);
    // warp reduce max
    #pragma unroll
    for (int off = 16; off > 0; off >>= 1)
        runMax = fmaxf(runMax, __shfl_xor_sync(0xffffffffu, runMax, off));
    const int lane = t & 31;
    const int wid  = t >> 5;
    if (lane == 0) wmax[wid] = runMax;
    __syncthreads();

    // T = 5th largest of the 8 warp maxes
    if (t == 0) {
        float a0=wmax[0],a1=wmax[1],a2=wmax[2],a3=wmax[3],
              a4=wmax[4],a5=wmax[5],a6=wmax[6],a7=wmax[7];
        float T = 0.0f;
        #pragma unroll
        for (int r = 0; r < 5; r++) {
            float mx = fmaxf(fmaxf(fmaxf(a0,a1),fmaxf(a2,a3)),
                             fmaxf(fmaxf(a4,a5),fmaxf(a6,a7)));
            T = mx;
            // remove one occurrence of mx
            if      (a0==mx) a0=-FLT_MAX; else if (a1==mx) a1=-FLT_MAX;
            else if (a2==mx) a2=-FLT_MAX; else if (a3==mx) a3=-FLT_MAX;
            else if (a4==mx) a4=-FLT_MAX; else if (a5==mx) a5=-FLT_MAX;
            else if (a6==mx) a6=-FLT_MAX; else a7=-FLT_MAX;
        }
        sTh = T;
    }
    __syncthreads();
    const float T = sTh;

    // ================= Pass B: sparse candidate collection =================
    #pragma unroll
    for (int i = 0; i < NCHUNK; i++) {
        if (schunk[(i << 8) + t] >= T) {         // rare: ~17 chunks per block
            const int e = t + (i << 10);
            #pragma unroll
            for (int s = 0; s < 4; s++) {
                const int ee = e + s * 256;
                float4 x = base4[ee];
                const int gb = pre + 4 * ee;
                float xv[4] = {x.x, x.y, x.z, x.w};
                #pragma unroll
                for (int c = 0; c < 4; c++) {
                    if (xv[c] >= T) {
                        int slot = atomicAdd(&scnt, 1);
                        if (slot < CANDCAP) { bv[slot] = xv[c]; bi[slot] = gb + c; }
                    }
                }
            }
        }
    }
    // remainder float4s
    for (int e = (NCHUNK << 10) + t; e < n4; e += 256) {
        float4 x = base4[e];
        if (max4(x) >= T) {
            const int gb = pre + 4 * e;
            float xv[4] = {x.x, x.y, x.z, x.w};
            #pragma unroll
            for (int c = 0; c < 4; c++) {
                if (xv[c] >= T) {
                    int slot = atomicAdd(&scnt, 1);
                    if (slot < CANDCAP) { bv[slot] = xv[c]; bi[slot] = gb + c; }
                }
            }
        }
    }
    // scalar prefix / tail
    if (t < pre) {
        float x = rowp[t];
        if (x >= T) {
            int slot = atomicAdd(&scnt, 1);
            if (slot < CANDCAP) { bv[slot] = x; bi[slot] = t; }
        }
    }
    if (t >= 32 && t < 32 + ntail) {
        int e = tail_start + (t - 32);
        float x = rowp[e];
        if (x >= T) {
            int slot = atomicAdd(&scnt, 1);
            if (slot < CANDCAP) { bv[slot] = x; bi[slot] = e; }
        }
    }
    __syncthreads();

    const int n = (scnt < CANDCAP) ? scnt : CANDCAP;   // guaranteed >= 5

    // ================= 5 rounds of block argmax over candidates =================
    __shared__ float wmv[8];
    __shared__ int   wmp[8];
    for (int r = 0; r < TOPK; r++) {
        float bm = -FLT_MAX; int bp = 0;
        #pragma unroll
        for (int s = 0; s < CANDCAP; s += 256) {
            int idx = t + s;
            float v = (idx < n) ? bv[idx] : -FLT_MAX;
            if (v > bm) { bm = v; bp = idx; }
        }
        #pragma unroll
        for (int off = 16; off > 0; off >>= 1) {
            float ov = __shfl_down_sync(0xffffffffu, bm, off);
            int   op = __shfl_down_sync(0xffffffffu, bp, off);
            if (ov > bm) { bm = ov; bp = op; }
        }
        if (lane == 0) { wmv[wid] = bm; wmp[wid] = bp; }
        __syncthreads();
        if (t == 0) {
            float gm = wmv[0]; int gp = wmp[0];
            #pragma unroll
            for (int w = 1; w < 8; w++)
                if (wmv[w] > gm) { gm = wmv[w]; gp = wmp[w]; }
            fv[r] = gm;
            fi[r] = bi[gp];
            bv[gp] = -FLT_MAX;
        }
        __syncthreads();
    }

    // ---- softmax over 5 (fv sorted desc so fv[0] is the max) ----
    float mx = fv[0];
    float p0 = __expf(fv[0]-mx), p1 = __expf(fv[1]-mx), p2 = __expf(fv[2]-mx),
          p3 = __expf(fv[3]-mx), p4 = __expf(fv[4]-mx);
    float inv = 1.0f / (p0+p1+p2+p3+p4);
    p0*=inv; p1*=inv; p2*=inv; p3*=inv; p4*=inv;

    const float* e0 = embed_table + (size_t)fi[0]*D;
    const float* e1 = embed_table + (size_t)fi[1]*D;
    const float* e2 = embed_table + (size_t)fi[2]*D;
    const float* e3 = embed_table + (size_t)fi[3]*D;
    const float* e4 = embed_table + (size_t)fi[4]*D;

    float* sce = g_sce + (size_t)row * D;
    #pragma unroll
    for (int j = 0; j < 3; j++) {
        int d = t + j*256;
        sce[d] = p0*e0[d] + p1*e1[d] + p2*e2[d] + p3*e3[d] + p4*e4[d];
    }
}

// ---------------------------------------------------------------------------
// Kernel 2: attention. Block = (b, query-pair). Grid 256, 256 threads.
// ---------------------------------------------------------------------------
__global__ __launch_bounds__(256) void attn_kernel(
    const float* __restrict__ q_in,          // [16,32,768]
    const int*   __restrict__ caption_len)   // [16]
{
    const int b  = blockIdx.x >> 4;
    const int qg = blockIdx.x & 15;          // queries qg*2, qg*2+1
    const int t  = threadIdx.x;

    const float* sce = g_sce + (size_t)b * CAP * D;

    __shared__ float sq[2 * QPAD];
    __shared__ float ssc[2][CAP];

    // stage the 2 query rows with padded stride
    {
        const float4* qg4 = (const float4*)(q_in + ((size_t)b * AT + qg*2) * D);
        for (int i = t; i < 2 * (D/4); i += 256) {
            int qi = i / (D/4), j = i % (D/4);
            *(float4*)&sq[qi * QPAD + j * 4] = qg4[qi * (D/4) + j];
        }
    }
    __syncthreads();

    // scores: 128 (q,k) pairs; threads 0..127, qi = t&1, k = t>>1
    if (t < 128) {
        const int qi = t & 1;
        const int k  = t >> 1;
        const float4* krow = (const float4*)(sce + (size_t)k * D);
        const float4* qrow = (const float4*)(sq + qi * QPAD);
        float a0 = 0.f, a1 = 0.f, a2 = 0.f, a3 = 0.f;
        #pragma unroll 4
        for (int j = 0; j < D/4; j++) {
            float4 kk = krow[j];
            float4 qq = qrow[j];
            a0 = fmaf(kk.x, qq.x, a0);
            a1 = fmaf(kk.y, qq.y, a1);
            a2 = fmaf(kk.z, qq.z, a2);
            a3 = fmaf(kk.w, qq.w, a3);
        }
        ssc[qi][k] = (a0 + a1) + (a2 + a3);
    }
    __syncthreads();

    // softmax per query row; warps 0-1 handle rows 0-1
    const int w = t >> 5, lane = t & 31;
    const int clen = caption_len[b];
    if (w < 2) {
        const float scale = 1.0f / sqrtf((float)D);
        float s0 = (lane      < clen) ? ssc[w][lane]      * scale : -1e9f;
        float s1 = (lane + 32 < clen) ? ssc[w][lane + 32] * scale : -1e9f;
        float mx = fmaxf(s0, s1);
        #pragma unroll
        for (int off = 16; off > 0; off >>= 1)
            mx = fmaxf(mx, __shfl_xor_sync(0xffffffffu, mx, off));
        float e0 = __expf(s0 - mx), e1 = __expf(s1 - mx);
        float sum = e0 + e1;
        #pragma unroll
        for (int off = 16; off > 0; off >>= 1)
            sum += __shfl_xor_sync(0xffffffffu, sum, off);
        float isum = 1.0f / sum;
        ssc[w][lane]      = e0 * isum;
        ssc[w][lane + 32] = e1 * isum;
    }
    __syncthreads();

    // output: thread owns dims t, t+256, t+512 for both queries (coalesced)
    float acc[2][3];
    #pragma unroll
    for (int qi = 0; qi < 2; qi++) { acc[qi][0]=0; acc[qi][1]=0; acc[qi][2]=0; }

    #pragma unroll 4
    for (int k = 0; k < CAP; k++) {
        const float* srow = sce + (size_t)k * D;
        float a0 = srow[t], a1 = srow[t + 256], a2 = srow[t + 512];
        #pragma unroll
        for (int qi = 0; qi < 2; qi++) {
            float aw = ssc[qi][k];
            acc[qi][0] = fmaf(aw, a0, acc[qi][0]);
            acc[qi][1] = fmaf(aw, a1, acc[qi][1]);
            acc[qi][2] = fmaf(aw, a2, acc[qi][2]);
        }
    }
    #pragma unroll
    for (int qi = 0; qi < 2; qi++) {
        float* orow = g_att + ((size_t)b * AT + qg*2 + qi) * D;
        orow[t]       = acc[qi][0];
        orow[t + 256] = acc[qi][1];
        orow[t + 512] = acc[qi][2];
    }
}

// ---------------------------------------------------------------------------
// Kernel 3: final assembly. Block per (b,s). Grid 4096, 192 threads (float4).
// ---------------------------------------------------------------------------
__global__ __launch_bounds__(192) void assemble_kernel(
    const float* __restrict__ embed_table,
    const int*   __restrict__ input_ids,     // [16,256]
    const int*   __restrict__ origin_len,    // [16]
    const int*   __restrict__ target_len,    // [16]
    float*       __restrict__ out)           // [16,256,768]
{
    const int bs = blockIdx.x;
    const int b  = bs >> 8;
    const int s  = bs & 255;
    const int rel = s - origin_len[b];
    const int tl  = target_len[b];

    const float* src;
    if (rel >= 0 && rel < tl)      src = g_att + ((size_t)b * AT + rel) * D;
    else if (rel == tl)            src = embed_table + (size_t)END_ID * D;
    else                           src = embed_table + (size_t)input_ids[bs] * D;

    ((float4*)(out + (size_t)bs * D))[threadIdx.x] = ((const float4*)src)[threadIdx.x];
}

// ---------------------------------------------------------------------------
extern "C" void kernel_launch(void* const* d_in, const int* in_sizes, int n_in,
                              void* d_out, int out_size)
{
    const float* caption_out      = (const float*)d_in[0];   // [16,64,50265]
    const float* embed_table      = (const float*)d_in[1];   // [50265,768]
    const float* inputs_embeds_at = (const float*)d_in[2];   // [16,32,768]
    const int*   input_ids        = (const int*)  d_in[3];   // [16,256]
    const int*   origin_len       = (const int*)  d_in[4];   // [16]
    const int*   target_len       = (const int*)  d_in[5];   // [16]
    const int*   caption_len      = (const int*)  d_in[6];   // [16]
    float* out = (float*)d_out;

    topk_sce_kernel<<<BS * CAP, 256>>>(caption_out, embed_table);
    attn_kernel<<<BS * 16, 256>>>(inputs_embeds_at, caption_len);
    assemble_kernel<<<BS * SEQ, 192>>>(embed_table, input_ids,
                                       origin_len, target_len, out);
}

// round 9
// speedup vs baseline: 2.8376x; 1.2430x over previous
#include <cuda_runtime.h>
#include <cuda_bf16.h>
#include <cfloat>
#include <math.h>

// Problem constants
#define BS    16
#define CAP   64
#define VOCAB 50265
#define TOPK  5
#define SEQ   256
#define AT    32
#define D     768
#define END_ID 2

#define QPAD  772      // padded q-row stride in floats
#define NCHUNK 12      // 12 * 1024 float4s in chunked region
#define CANDCAP 512    // candidate buffer capacity

// Scratch (device globals — no allocation allowed)
__device__ float g_sce[BS * CAP * D];   // [16,64,768]
__device__ float g_att[BS * AT * D];    // [16,32,768]

__device__ __forceinline__ float max4(const float4& x) {
    return fmaxf(fmaxf(x.x, x.y), fmaxf(x.z, x.w));
}

// ---------------------------------------------------------------------------
// Kernel 1: per (b,c) row — top-5 over vocab, softmax, weighted embed gather.
// Grid: 1024 blocks, 256 threads, FORCED 8 blocks/SM -> single wave.
// ---------------------------------------------------------------------------
__global__ __launch_bounds__(256, 8) void topk_sce_kernel(
    const float* __restrict__ caption_out,   // [16,64,VOCAB]
    const float* __restrict__ embed_table)   // [VOCAB, D]
{
    const int row = blockIdx.x;              // 0..1023  (= b*CAP + c)
    const int t   = threadIdx.x;
    const float* rowp = caption_out + (size_t)row * VOCAB;

    __shared__ float schunk[NCHUNK * 256];   // per-chunk maxes (12 KB)
    __shared__ float bv[CANDCAP];
    __shared__ int   bi[CANDCAP];
    __shared__ int   scnt;
    __shared__ float wmax[8];
    __shared__ float sTh;
    __shared__ float fv[TOPK];
    __shared__ int   fi[TOPK];

    if (t == 0) scnt = 0;

    // alignment prologue
    const int mis = (int)(((size_t)rowp >> 2) & 3);
    const int pre = (4 - mis) & 3;                    // scalar prefix (0..3)
    const int n4  = (VOCAB - pre) >> 2;               // aligned float4 count
    const int tail_start = pre + (n4 << 2);
    const int ntail = VOCAB - tail_start;             // 0..3
    const float4* base4 = (const float4*)(rowp + pre);

    // ================= Pass A: branchless max scan =================
    float m0 = -FLT_MAX, m1 = -FLT_MAX;
    #pragma unroll 2
    for (int i = 0; i < NCHUNK; i++) {
        const int e = t + (i << 10);
        float4 x0 = base4[e];
        float4 x1 = base4[e + 256];
        float4 x2 = base4[e + 512];
        float4 x3 = base4[e + 768];
        float cm = fmaxf(fmaxf(max4(x0), max4(x1)), fmaxf(max4(x2), max4(x3)));
        schunk[(i << 8) + t] = cm;
        m0 = fmaxf(m0, cm);
    }
    for (int e = (NCHUNK << 10) + t; e < n4; e += 256)
        m1 = fmaxf(m1, max4(base4[e]));
    if (t < pre) m1 = fmaxf(m1, rowp[t]);
    if (t >= 32 && t < 32 + ntail) m1 = fmaxf(m1, rowp[tail_start + (t - 32)]);

    float runMax = fmaxf(m0, m1);
    #pragma unroll
    for (int off = 16; off > 0; off >>= 1)
        runMax = fmaxf(runMax, __shfl_xor_sync(0xffffffffu, runMax, off));
    const int lane = t & 31;
    const int wid  = t >> 5;
    if (lane == 0) wmax[wid] = runMax;
    __syncthreads();

    // T = 5th largest of the 8 warp maxes (>=5 distinct elements >= T exist)
    if (t == 0) {
        float a0=wmax[0],a1=wmax[1],a2=wmax[2],a3=wmax[3],
              a4=wmax[4],a5=wmax[5],a6=wmax[6],a7=wmax[7];
        float T = 0.0f;
        #pragma unroll
        for (int r = 0; r < 5; r++) {
            float mx = fmaxf(fmaxf(fmaxf(a0,a1),fmaxf(a2,a3)),
                             fmaxf(fmaxf(a4,a5),fmaxf(a6,a7)));
            T = mx;
            if      (a0==mx) a0=-FLT_MAX; else if (a1==mx) a1=-FLT_MAX;
            else if (a2==mx) a2=-FLT_MAX; else if (a3==mx) a3=-FLT_MAX;
            else if (a4==mx) a4=-FLT_MAX; else if (a5==mx) a5=-FLT_MAX;
            else if (a6==mx) a6=-FLT_MAX; else a7=-FLT_MAX;
        }
        sTh = T;
    }
    __syncthreads();
    const float T = sTh;

    // ================= Pass B: sparse candidate collection =================
    #pragma unroll
    for (int i = 0; i < NCHUNK; i++) {
        if (schunk[(i << 8) + t] >= T) {         // rare: ~17 chunks per block
            const int e = t + (i << 10);
            #pragma unroll
            for (int s = 0; s < 4; s++) {
                const int ee = e + s * 256;
                float4 x = base4[ee];
                const int gb = pre + 4 * ee;
                float xv[4] = {x.x, x.y, x.z, x.w};
                #pragma unroll
                for (int c = 0; c < 4; c++) {
                    if (xv[c] >= T) {
                        int slot = atomicAdd(&scnt, 1);
                        if (slot < CANDCAP) { bv[slot] = xv[c]; bi[slot] = gb + c; }
                    }
                }
            }
        }
    }
    for (int e = (NCHUNK << 10) + t; e < n4; e += 256) {
        float4 x = base4[e];
        if (max4(x) >= T) {
            const int gb = pre + 4 * e;
            float xv[4] = {x.x, x.y, x.z, x.w};
            #pragma unroll
            for (int c = 0; c < 4; c++) {
                if (xv[c] >= T) {
                    int slot = atomicAdd(&scnt, 1);
                    if (slot < CANDCAP) { bv[slot] = xv[c]; bi[slot] = gb + c; }
                }
            }
        }
    }
    if (t < pre) {
        float x = rowp[t];
        if (x >= T) {
            int slot = atomicAdd(&scnt, 1);
            if (slot < CANDCAP) { bv[slot] = x; bi[slot] = t; }
        }
    }
    if (t >= 32 && t < 32 + ntail) {
        int e = tail_start + (t - 32);
        float x = rowp[e];
        if (x >= T) {
            int slot = atomicAdd(&scnt, 1);
            if (slot < CANDCAP) { bv[slot] = x; bi[slot] = e; }
        }
    }
    __syncthreads();

    const int n = (scnt < CANDCAP) ? scnt : CANDCAP;   // guaranteed >= 5

    // ================= 5 rounds of block argmax over candidates =================
    __shared__ float wmv[8];
    __shared__ int   wmp[8];
    for (int r = 0; r < TOPK; r++) {
        float bm = -FLT_MAX; int bp = 0;
        #pragma unroll
        for (int s = 0; s < CANDCAP; s += 256) {
            int idx = t + s;
            float v = (idx < n) ? bv[idx] : -FLT_MAX;
            if (v > bm) { bm = v; bp = idx; }
        }
        #pragma unroll
        for (int off = 16; off > 0; off >>= 1) {
            float ov = __shfl_down_sync(0xffffffffu, bm, off);
            int   op = __shfl_down_sync(0xffffffffu, bp, off);
            if (ov > bm) { bm = ov; bp = op; }
        }
        if (lane == 0) { wmv[wid] = bm; wmp[wid] = bp; }
        __syncthreads();
        if (t == 0) {
            float gm = wmv[0]; int gp = wmp[0];
            #pragma unroll
            for (int w = 1; w < 8; w++)
                if (wmv[w] > gm) { gm = wmv[w]; gp = wmp[w]; }
            fv[r] = gm;
            fi[r] = bi[gp];
            bv[gp] = -FLT_MAX;
        }
        __syncthreads();
    }

    // ---- softmax over 5 + weighted embed gather ----
    float mx = fv[0];
    float p0 = __expf(fv[0]-mx), p1 = __expf(fv[1]-mx), p2 = __expf(fv[2]-mx),
          p3 = __expf(fv[3]-mx), p4 = __expf(fv[4]-mx);
    float inv = 1.0f / (p0+p1+p2+p3+p4);
    p0*=inv; p1*=inv; p2*=inv; p3*=inv; p4*=inv;

    const float* e0 = embed_table + (size_t)fi[0]*D;
    const float* e1 = embed_table + (size_t)fi[1]*D;
    const float* e2 = embed_table + (size_t)fi[2]*D;
    const float* e3 = embed_table + (size_t)fi[3]*D;
    const float* e4 = embed_table + (size_t)fi[4]*D;

    float* sce = g_sce + (size_t)row * D;
    #pragma unroll
    for (int j = 0; j < 3; j++) {
        int d = t + j*256;
        sce[d] = p0*e0[d] + p1*e1[d] + p2*e2[d] + p3*e3[d] + p4*e4[d];
    }
}

// ---------------------------------------------------------------------------
// Kernel 2: attention. Block = (b, query-group of 4). Grid 128, 256 threads.
// Score phase: warp-per-key, coalesced k-row loads, 4 query dots + butterfly.
// ---------------------------------------------------------------------------
__global__ __launch_bounds__(256) void attn_kernel(
    const float* __restrict__ q_in,          // [16,32,768]
    const int*   __restrict__ caption_len)   // [16]
{
    const int b  = blockIdx.x >> 3;
    const int qg = blockIdx.x & 7;           // queries qg*4 .. qg*4+3
    const int t  = threadIdx.x;
    const int wid  = t >> 5;
    const int lane = t & 31;

    const float* sce = g_sce + (size_t)b * CAP * D;

    __shared__ float sq[4 * QPAD];
    __shared__ float ssc[4][CAP];

    // stage the 4 query rows with padded stride
    {
        const float4* qg4 = (const float4*)(q_in + ((size_t)b * AT + qg*4) * D);
        for (int i = t; i < 4 * (D/4); i += 256) {
            int qi = i / (D/4), j = i % (D/4);
            *(float4*)&sq[qi * QPAD + j * 4] = qg4[qi * (D/4) + j];
        }
    }
    __syncthreads();

    // scores: warp w handles keys w, w+8, ..., w+56
    #pragma unroll
    for (int kb = 0; kb < 8; kb++) {
        const int k = kb * 8 + wid;
        const float4* krow = (const float4*)(sce + (size_t)k * D);
        float a0 = 0.f, a1 = 0.f, a2 = 0.f, a3 = 0.f;
        #pragma unroll
        for (int i = 0; i < 6; i++) {
            const int j = lane + 32 * i;       // float4 index, 0..191
            float4 kk = krow[j];
            float4 q0 = *(const float4*)&sq[0*QPAD + j*4];
            float4 q1 = *(const float4*)&sq[1*QPAD + j*4];
            float4 q2 = *(const float4*)&sq[2*QPAD + j*4];
            float4 q3 = *(const float4*)&sq[3*QPAD + j*4];
            a0 = fmaf(kk.x,q0.x, fmaf(kk.y,q0.y, fmaf(kk.z,q0.z, fmaf(kk.w,q0.w, a0))));
            a1 = fmaf(kk.x,q1.x, fmaf(kk.y,q1.y, fmaf(kk.z,q1.z, fmaf(kk.w,q1.w, a1))));
            a2 = fmaf(kk.x,q2.x, fmaf(kk.y,q2.y, fmaf(kk.z,q2.z, fmaf(kk.w,q2.w, a2))));
            a3 = fmaf(kk.x,q3.x, fmaf(kk.y,q3.y, fmaf(kk.z,q3.z, fmaf(kk.w,q3.w, a3))));
        }
        #pragma unroll
        for (int off = 16; off > 0; off >>= 1) {
            a0 += __shfl_xor_sync(0xffffffffu, a0, off);
            a1 += __shfl_xor_sync(0xffffffffu, a1, off);
            a2 += __shfl_xor_sync(0xffffffffu, a2, off);
            a3 += __shfl_xor_sync(0xffffffffu, a3, off);
        }
        if (lane == 0) {
            ssc[0][k] = a0; ssc[1][k] = a1; ssc[2][k] = a2; ssc[3][k] = a3;
        }
    }
    __syncthreads();

    // softmax per query row; warps 0-3 handle rows 0-3
    const int clen = caption_len[b];
    if (wid < 4) {
        const float scale = 1.0f / sqrtf((float)D);
        float s0 = (lane      < clen) ? ssc[wid][lane]      * scale : -1e9f;
        float s1 = (lane + 32 < clen) ? ssc[wid][lane + 32] * scale : -1e9f;
        float mx = fmaxf(s0, s1);
        #pragma unroll
        for (int off = 16; off > 0; off >>= 1)
            mx = fmaxf(mx, __shfl_xor_sync(0xffffffffu, mx, off));
        float e0 = __expf(s0 - mx), e1 = __expf(s1 - mx);
        float sum = e0 + e1;
        #pragma unroll
        for (int off = 16; off > 0; off >>= 1)
            sum += __shfl_xor_sync(0xffffffffu, sum, off);
        float isum = 1.0f / sum;
        ssc[wid][lane]      = e0 * isum;
        ssc[wid][lane + 32] = e1 * isum;
    }
    __syncthreads();

    // output: thread owns dims t, t+256, t+512 for all 4 queries (coalesced)
    float acc[4][3];
    #pragma unroll
    for (int qi = 0; qi < 4; qi++) { acc[qi][0]=0; acc[qi][1]=0; acc[qi][2]=0; }

    #pragma unroll 2
    for (int k = 0; k < CAP; k++) {
        const float* srow = sce + (size_t)k * D;
        float a0 = srow[t], a1 = srow[t + 256], a2 = srow[t + 512];
        #pragma unroll
        for (int qi = 0; qi < 4; qi++) {
            float aw = ssc[qi][k];
            acc[qi][0] = fmaf(aw, a0, acc[qi][0]);
            acc[qi][1] = fmaf(aw, a1, acc[qi][1]);
            acc[qi][2] = fmaf(aw, a2, acc[qi][2]);
        }
    }
    #pragma unroll
    for (int qi = 0; qi < 4; qi++) {
        float* orow = g_att + ((size_t)b * AT + qg*4 + qi) * D;
        orow[t]       = acc[qi][0];
        orow[t + 256] = acc[qi][1];
        orow[t + 512] = acc[qi][2];
    }
}

// ---------------------------------------------------------------------------
// Kernel 3: final assembly. Block per (b,s). Grid 4096, 192 threads (float4).
// ---------------------------------------------------------------------------
__global__ __launch_bounds__(192) void assemble_kernel(
    const float* __restrict__ embed_table,
    const int*   __restrict__ input_ids,     // [16,256]
    const int*   __restrict__ origin_len,    // [16]
    const int*   __restrict__ target_len,    // [16]
    float*       __restrict__ out)           // [16,256,768]
{
    const int bs = blockIdx.x;
    const int b  = bs >> 8;
    const int s  = bs & 255;
    const int rel = s - origin_len[b];
    const int tl  = target_len[b];

    const float* src;
    if (rel >= 0 && rel < tl)      src = g_att + ((size_t)b * AT + rel) * D;
    else if (rel == tl)            src = embed_table + (size_t)END_ID * D;
    else                           src = embed_table + (size_t)input_ids[bs] * D;

    ((float4*)(out + (size_t)bs * D))[threadIdx.x] = ((const float4*)src)[threadIdx.x];
}

// ---------------------------------------------------------------------------
extern "C" void kernel_launch(void* const* d_in, const int* in_sizes, int n_in,
                              void* d_out, int out_size)
{
    const float* caption_out      = (const float*)d_in[0];   // [16,64,50265]
    const float* embed_table      = (const float*)d_in[1];   // [50265,768]
    const float* inputs_embeds_at = (const float*)d_in[2];   // [16,32,768]
    const int*   input_ids        = (const int*)  d_in[3];   // [16,256]
    const int*   origin_len       = (const int*)  d_in[4];   // [16]
    const int*   target_len       = (const int*)  d_in[5];   // [16]
    const int*   caption_len      = (const int*)  d_in[6];   // [16]
    float* out = (float*)d_out;

    topk_sce_kernel<<<BS * CAP, 256>>>(caption_out, embed_table);
    attn_kernel<<<BS * 8, 256>>>(inputs_embeds_at, caption_len);
    assemble_kernel<<<BS * SEQ, 192>>>(embed_table, input_ids,
                                       origin_len, target_len, out);
}